// round 9
// baseline (speedup 1.0000x reference)
#include <cuda_runtime.h>
#include <cuda_bf16.h>
#include <math.h>
#include <stdint.h>

// Problem constants
#define B  32768
#define K  8192
#define D  1024
#define DECAY   0.99f
#define ONE_M_D 0.01f
#define EPS     1e-5f
#define COMMIT  0.25f
#define NORM_EPS 1e-12f

// Candidate machinery
#define CAP    64
#define MARGIN 0.15f

// Output layout (flattened tuple, float32)
#define OFF_ZQ   0
#define OFF_IDS  (B*D)
#define OFF_LOSS (OFF_IDS + B)
#define OFF_CB   (OFF_LOSS + 1)              // odd -> no float4 stores
#define OFF_CNT  (OFF_CB + K*D)
#define OFF_W    (OFF_CNT + K)               // odd -> no float4 stores

// -------------------- device scratch (no allocation allowed) ----------------
__device__ __align__(16) __nv_bfloat16 g_a0[(size_t)B * D];   // bf16(z)
__device__ __align__(16) __nv_bfloat16 g_b0[(size_t)K * D];   // bf16(cb_norm)
__device__ __align__(16) float g_cbn[(size_t)K * D];          // fp32 cb_norm
__device__ __align__(16) float g_wsum[K * D];
__device__ int   g_cand[(size_t)B * CAP];
__device__ int   g_ccnt[B];
__device__ float g_cnt[K];
__device__ float g_ncnt[K];
__device__ int   g_ids[B];
__device__ float g_loss;

// -------------------- PTX helpers (compute_103-safe) ------------------------
__device__ __forceinline__ uint32_t smem_u32(const void* p) {
    uint32_t a;
    asm("{ .reg .u64 t; cvta.to.shared.u64 t, %1; cvt.u32.u64 %0, t; }"
        : "=r"(a) : "l"(p));
    return a;
}
__device__ __forceinline__ void cp_async16(uint32_t dst, const void* src) {
    asm volatile("cp.async.cg.shared.global [%0], [%1], 16;"
                 :: "r"(dst), "l"(src) : "memory");
}
__device__ __forceinline__ void cp_commit() {
    asm volatile("cp.async.commit_group;" ::: "memory");
}
template <int N> __device__ __forceinline__ void cp_wait() {
    asm volatile("cp.async.wait_group %0;" :: "n"(N) : "memory");
}
__device__ __forceinline__ void ldsm4(uint32_t& r0, uint32_t& r1,
                                      uint32_t& r2, uint32_t& r3, uint32_t a) {
    asm volatile("ldmatrix.sync.aligned.m8n8.x4.shared.b16 {%0,%1,%2,%3}, [%4];"
                 : "=r"(r0), "=r"(r1), "=r"(r2), "=r"(r3) : "r"(a));
}
__device__ __forceinline__ void mma16816(float* c, const uint32_t* a,
                                         const uint32_t* b) {
    asm volatile(
        "mma.sync.aligned.m16n8k16.row.col.f32.bf16.bf16.f32 "
        "{%0,%1,%2,%3}, {%4,%5,%6,%7}, {%8,%9}, {%0,%1,%2,%3};"
        : "+f"(c[0]), "+f"(c[1]), "+f"(c[2]), "+f"(c[3])
        : "r"(a[0]), "r"(a[1]), "r"(a[2]), "r"(a[3]), "r"(b[0]), "r"(b[1]));
}
#define SW128(x) ((x) ^ (((x) >> 3) & 0x70))

// order-preserving float<->uint for atomicMax
__device__ __forceinline__ unsigned fenc(float f) {
    unsigned u = __float_as_uint(f);
    return (u & 0x80000000u) ? ~u : (u | 0x80000000u);
}
__device__ __forceinline__ float fdec(unsigned u) {
    return (u & 0x80000000u) ? __uint_as_float(u ^ 0x80000000u)
                             : __uint_as_float(~u);
}

// -------------------- setup kernels -----------------------------------------
__global__ void k_zero() {
    int64_t tid = (int64_t)blockIdx.x * blockDim.x + threadIdx.x;
    int64_t stride = (int64_t)gridDim.x * blockDim.x;
    for (int64_t i = tid; i < (int64_t)K * D; i += stride) g_wsum[i] = 0.0f;
    for (int64_t i = tid; i < K; i += stride) g_cnt[i] = 0.0f;
    for (int64_t i = tid; i < B; i += stride) g_ccnt[i] = 0;
    if (tid == 0) g_loss = 0.0f;
}

__global__ void k_cast_z(const float* __restrict__ z) {
    int64_t i = (int64_t)blockIdx.x * blockDim.x + threadIdx.x;
    int64_t n4 = (int64_t)B * D / 4;
    int64_t stride = (int64_t)gridDim.x * blockDim.x;
    for (; i < n4; i += stride) {
        float4 v = ((const float4*)z)[i];
        __nv_bfloat162* p = (__nv_bfloat162*)g_a0 + i * 2;
        __nv_bfloat162 t;
        t.x = __float2bfloat16_rn(v.x); t.y = __float2bfloat16_rn(v.y); p[0] = t;
        t.x = __float2bfloat16_rn(v.z); t.y = __float2bfloat16_rn(v.w); p[1] = t;
    }
}

// normalize codebook rows -> fp32 g_cbn + bf16 g_b0. one block per row.
__global__ void k_norm_cb(const float* __restrict__ cb) {
    __shared__ float red[256];
    int k = blockIdx.x;
    int t = threadIdx.x;
    float4 v = ((const float4*)(cb + (size_t)k * D))[t];
    red[t] = v.x * v.x + v.y * v.y + v.z * v.z + v.w * v.w;
    __syncthreads();
    for (int s = 128; s > 0; s >>= 1) {
        if (t < s) red[t] += red[t + s];
        __syncthreads();
    }
    float denom = fmaxf(sqrtf(red[0]), NORM_EPS);
    float4 o;
    o.x = v.x / denom; o.y = v.y / denom; o.z = v.z / denom; o.w = v.w / denom;
    ((float4*)(g_cbn + (size_t)k * D))[t] = o;
    __nv_bfloat162* p = (__nv_bfloat162*)g_b0 + (size_t)k * (D / 2) + t * 2;
    __nv_bfloat162 x;
    x.x = __float2bfloat16_rn(o.x); x.y = __float2bfloat16_rn(o.y); p[0] = x;
    x.x = __float2bfloat16_rn(o.z); x.y = __float2bfloat16_rn(o.w); p[1] = x;
}

// -------------------- approx bf16 GEMM + candidate harvest ------------------
// CTA: 128 rows, sweeps 64 N-tiles of 128. 8 warps = 4(M) x 2(N), warp 32x64.
// Continuous chunk stream t = nt*NDK+dk over a 3-stage cp.async pipeline,
// ONE __syncthreads per chunk; prefetch t+2 issued after chunk t's MMAs so
// next-tile loads overlap the candidate-harvest epilogue.
#define DKC   64
#define NDK   (D / DKC)               // 16
#define NT    (K / 128)               // 64
#define NCHUNK (NT * NDK)             // 1024
#define TILE_B 8192                   // 128 rows x 64 cols bf16 = 16KB? no: 128*128B
#undef  TILE_B
#define TILE_B 16384                  // 128 rows x 128 bytes (64 bf16 cols)
#define STAGE_B (2 * TILE_B)          // A chunk + B chunk = 32 KB
#define STAGES 3
#define DYN_SMEM (STAGES * STAGE_B)   // 96 KB

// issue the 8 cp.async16 for chunk t into its stage
__device__ __forceinline__ void load_chunk(uint32_t sbase, int t, int tid,
                                           const __nv_bfloat16* asrc0) {
    int nt = t >> 4;
    int dk = t & 15;
    uint32_t sb = sbase + (t % STAGES) * STAGE_B;
    int koff = dk * DKC;
    const __nv_bfloat16* srcs[2] = {
        asrc0 + koff,
        g_b0 + (size_t)nt * 128 * D + koff };
#pragma unroll
    for (int t2 = 0; t2 < 2; t2++) {
        const __nv_bfloat16* src = srcs[t2];
#pragma unroll
        for (int it = 0; it < 4; it++) {
            int c = tid + 256 * it;
            int r = c >> 3, ch = c & 7;
            cp_async16(sb + t2 * TILE_B + SW128(r * 128 + ch * 16),
                       src + (size_t)r * D + ch * 8);
        }
    }
    cp_commit();
}

__global__ __launch_bounds__(256, 2)
void k_approx(int dummy) {
    extern __shared__ char dyn[];
    __shared__ unsigned srowmax[128];
    uint32_t sbase = smem_u32(dyn);

    int tid = threadIdx.x;
    int lane = tid & 31;
    int wid = tid >> 5;
    int warp_m = wid >> 1;            // 0..3
    int warp_n = wid & 1;             // 0..1
    int g = lane >> 2;                // 0..7
    int tig = lane & 3;               // 0..3
    int row0 = blockIdx.x * 128;

    int lm_r = lane & 15;
    int lm_c = (lane >> 4) << 4;

    if (tid < 128) srowmax[tid] = 0u;   // < fenc of any float
    __syncthreads();

    const __nv_bfloat16* asrc0 = g_a0 + (size_t)row0 * D;

    // prologue: chunks 0,1
    load_chunk(sbase, 0, tid, asrc0);
    load_chunk(sbase, 1, tid, asrc0);

    for (int nt = 0; nt < NT; nt++) {
        float acc[2][8][4];
#pragma unroll
        for (int i = 0; i < 2; i++)
#pragma unroll
            for (int j = 0; j < 8; j++)
#pragma unroll
                for (int q = 0; q < 4; q++) acc[i][j][q] = 0.0f;

        for (int dk = 0; dk < NDK; dk++) {
            int t = nt * NDK + dk;
            if (t == NCHUNK - 1) cp_wait<0>(); else cp_wait<1>();
            __syncthreads();

            uint32_t stg = sbase + (t % STAGES) * STAGE_B;
#pragma unroll
            for (int step = 0; step < 4; step++) {
                int kc = step * 32 + lm_c;
                uint32_t afr[2][4];
#pragma unroll
                for (int mi = 0; mi < 2; mi++) {
                    int r = warp_m * 32 + mi * 16 + lm_r;
                    uint32_t addr = stg + SW128(r * 128 + kc);
                    ldsm4(afr[mi][0], afr[mi][1], afr[mi][2], afr[mi][3], addr);
                }
                uint32_t bfr[4][4];
#pragma unroll
                for (int nb = 0; nb < 4; nb++) {
                    int r = warp_n * 64 + nb * 16 + lm_r;
                    uint32_t addr = stg + TILE_B + SW128(r * 128 + kc);
                    ldsm4(bfr[nb][0], bfr[nb][1], bfr[nb][2], bfr[nb][3], addr);
                }
#pragma unroll
                for (int mi = 0; mi < 2; mi++) {
#pragma unroll
                    for (int nb = 0; nb < 4; nb++) {
                        uint32_t b0[2] = { bfr[nb][0], bfr[nb][2] };
                        uint32_t b1[2] = { bfr[nb][1], bfr[nb][3] };
                        mma16816(acc[mi][nb * 2 + 0], afr[mi], b0);
                        mma16816(acc[mi][nb * 2 + 1], afr[mi], b1);
                    }
                }
            }

            // prefetch chunk t+2 (overwrites stage read at iter t-1; the
            // __syncthreads at top of this iter proved all warps left it)
            if (t + 2 < NCHUNK) load_chunk(sbase, t + 2, tid, asrc0);
        }

        // ---- epilogue: running max + candidate insert (tile loads for the
        // next nt are already in flight above this)
#pragma unroll
        for (int i = 0; i < 2; i++) {
#pragma unroll
            for (int kk = 0; kk < 2; kk++) {
                int lrow = warp_m * 32 + i * 16 + kk * 8 + g;
                float m = -INFINITY;
#pragma unroll
                for (int j = 0; j < 8; j++) {
                    m = fmaxf(m, acc[i][j][kk * 2 + 0]);
                    m = fmaxf(m, acc[i][j][kk * 2 + 1]);
                }
                atomicMax(&srowmax[lrow], fenc(m));
            }
        }
        __syncthreads();
#pragma unroll
        for (int i = 0; i < 2; i++) {
#pragma unroll
            for (int kk = 0; kk < 2; kk++) {
                int lrow = warp_m * 32 + i * 16 + kk * 8 + g;
                float thr = fdec(srowmax[lrow]) - MARGIN;
                // quick reject: does this thread have any candidate?
                float m = -INFINITY;
#pragma unroll
                for (int j = 0; j < 8; j++) {
                    m = fmaxf(m, acc[i][j][kk * 2 + 0]);
                    m = fmaxf(m, acc[i][j][kk * 2 + 1]);
                }
                if (m < thr) continue;
#pragma unroll
                for (int j = 0; j < 8; j++) {
#pragma unroll
                    for (int h = 0; h < 2; h++) {
                        float v = acc[i][j][kk * 2 + h];
                        if (v >= thr) {
                            int col = nt * 128 + warp_n * 64 + j * 8 + tig * 2 + h;
                            int grow = row0 + lrow;
                            int p = atomicAdd(&g_ccnt[grow], 1);
                            if (p < CAP) g_cand[(size_t)grow * CAP + p] = col;
                        }
                    }
                }
            }
        }
        // next iteration's top-of-loop __syncthreads orders srowmax reuse
    }
}

// -------------------- exact rescore: one warp per row -----------------------
__global__ __launch_bounds__(256)
void k_rescore(const float* __restrict__ z) {
    int row = blockIdx.x * 8 + (threadIdx.x >> 5);
    int lane = threadIdx.x & 31;
    int cnt = g_ccnt[row];
    if (cnt > CAP) cnt = CAP;

    float4 zr[8];
    const float4* zp = (const float4*)(z + (size_t)row * D);
#pragma unroll
    for (int i = 0; i < 8; i++) zr[i] = zp[i * 32 + lane];

    float bv = -INFINITY;
    int   bi = 0;
    for (int c = 0; c < cnt; c++) {
        int idx = g_cand[(size_t)row * CAP + c];
        const float4* cp = (const float4*)(g_cbn + (size_t)idx * D);
        float s = 0.0f;
#pragma unroll
        for (int i = 0; i < 8; i++) {
            float4 cv = cp[i * 32 + lane];
            s += zr[i].x * cv.x + zr[i].y * cv.y + zr[i].z * cv.z + zr[i].w * cv.w;
        }
#pragma unroll
        for (int o = 16; o > 0; o >>= 1) s += __shfl_xor_sync(0xFFFFFFFFu, s, o);
        if (s > bv || (s == bv && idx < bi)) { bv = s; bi = idx; }
    }
    if (lane == 0) g_ids[row] = bi;
}

// -------------------- epilogue kernels --------------------------------------
__global__ void k_scatter(const float* __restrict__ z,
                          const float* __restrict__ cb,
                          float* __restrict__ out) {
    __shared__ float red[256];
    int b = blockIdx.x;
    int t = threadIdx.x;
    int id = g_ids[b];

    float4 zv = ((const float4*)(z  + (size_t)b  * D))[t];
    float4 qv = ((const float4*)(cb + (size_t)id * D))[t];

    float4 zq;
    zq.x = zv.x + (qv.x - zv.x);
    zq.y = zv.y + (qv.y - zv.y);
    zq.z = zv.z + (qv.z - zv.z);
    zq.w = zv.w + (qv.w - zv.w);
    ((float4*)(out + OFF_ZQ + (size_t)b * D))[t] = zq;

    float dx = zv.x - qv.x, dy = zv.y - qv.y, dz = zv.z - qv.z, dw = zv.w - qv.w;
    red[t] = dx * dx + dy * dy + dz * dz + dw * dw;

    float* wrow = g_wsum + (size_t)id * D + t * 4;
    atomicAdd(wrow + 0, zv.x);
    atomicAdd(wrow + 1, zv.y);
    atomicAdd(wrow + 2, zv.z);
    atomicAdd(wrow + 3, zv.w);

    __syncthreads();
    for (int s = 128; s > 0; s >>= 1) {
        if (t < s) red[t] += red[t + s];
        __syncthreads();
    }
    if (t == 0) {
        atomicAdd(&g_loss, red[0]);
        atomicAdd(&g_cnt[id], 1.0f);
        out[OFF_IDS + b] = (float)id;
    }
}

__global__ void k_count(const float* __restrict__ ema_count,
                        float* __restrict__ out) {
    int k = blockIdx.x * blockDim.x + threadIdx.x;
    if (k < K) {
        float nc = DECAY * ema_count[k] + ONE_M_D * g_cnt[k];
        g_ncnt[k] = nc;
        out[OFF_CNT + k] = nc;
    }
}

__global__ void k_final(const float* __restrict__ ema_weight,
                        float* __restrict__ out) {
    int64_t i4 = (int64_t)blockIdx.x * blockDim.x + threadIdx.x;
    if (i4 >= (int64_t)K * D / 4) return;
    int row = (int)(i4 >> 8);
    float4 ew = ((const float4*)ema_weight)[i4];
    float4 ws = ((const float4*)g_wsum)[i4];
    float w0 = DECAY * ew.x + ONE_M_D * ws.x;
    float w1 = DECAY * ew.y + ONE_M_D * ws.y;
    float w2 = DECAY * ew.z + ONE_M_D * ws.z;
    float w3 = DECAY * ew.w + ONE_M_D * ws.w;
    int64_t base = i4 * 4;
    out[OFF_W + base + 0] = w0;
    out[OFF_W + base + 1] = w1;
    out[OFF_W + base + 2] = w2;
    out[OFF_W + base + 3] = w3;
    float denom = g_ncnt[row] + EPS;
    out[OFF_CB + base + 0] = w0 / denom;
    out[OFF_CB + base + 1] = w1 / denom;
    out[OFF_CB + base + 2] = w2 / denom;
    out[OFF_CB + base + 3] = w3 / denom;
}

__global__ void k_loss(float* __restrict__ out) {
    out[OFF_LOSS] = COMMIT * (g_loss / (float)((int64_t)B * D));
}

// ---------------------------------------------------------------------------
extern "C" void kernel_launch(void* const* d_in, const int* in_sizes, int n_in,
                              void* d_out, int out_size) {
    const float* z          = (const float*)d_in[0];
    const float* codebook   = (const float*)d_in[1];
    const float* ema_count  = (const float*)d_in[2];
    const float* ema_weight = (const float*)d_in[3];
    float* out = (float*)d_out;

    cudaFuncSetAttribute(k_approx, cudaFuncAttributeMaxDynamicSharedMemorySize,
                         DYN_SMEM);

    k_zero<<<2048, 256>>>();
    k_cast_z<<<4096, 256>>>(z);
    k_norm_cb<<<K, 256>>>(codebook);
    k_approx<<<B / 128, 256, DYN_SMEM>>>(0);
    k_rescore<<<B / 8, 256>>>(z);
    k_scatter<<<B, 256>>>(z, codebook, out);
    k_count<<<(K + 255) / 256, 256>>>(ema_count, out);
    k_final<<<(K * D / 4 + 255) / 256, 256>>>(ema_weight, out);
    k_loss<<<1, 1>>>(out);
}